// round 1
// baseline (speedup 1.0000x reference)
#include <cuda_runtime.h>
#include <cuda_bf16.h>
#include <math.h>

// Problem constants
#define BATCH 8
#define SEQ   2048
#define DIM   768
#define MROWS (BATCH * SEQ)   // 16384

// GEMM tiling
#define BM 128
#define BN 128
#define BK 16
#define TM 8
#define TN 8
#define PAD 4   // smem padding to reduce transpose-store bank conflicts

// ---------------------------------------------------------------------------
// Scratch (allocation-free contract: __device__ globals)
// ---------------------------------------------------------------------------
__device__ float g_Q[(size_t)MROWS * DIM];
__device__ float g_K[(size_t)MROWS * DIM];
__device__ float g_V[(size_t)MROWS * DIM];
__device__ float g_O[(size_t)MROWS * DIM];
__device__ float g_alpha[(size_t)BATCH * SEQ * SEQ];

// ---------------------------------------------------------------------------
// SGEMM: C[m,n] = scale * sum_k A[m,k] * B'[k,n]  (+ bias[n])
//   TRANSB=true : B is [N,K] row-major (B'[k,n] = B[n,k])  -- x @ W^T, Q @ K^T
//   TRANSB=false: B is [K,N] row-major                     -- alpha @ V
// M,N multiples of 128; K multiple of 16. Batched via blockIdx.z + strides.
// ---------------------------------------------------------------------------
template<bool TRANSB>
__global__ void __launch_bounds__(256) sgemm_kernel(
    const float* __restrict__ A, const float* __restrict__ Bp,
    const float* __restrict__ bias, float* __restrict__ C,
    int M, int N, int K, float scale,
    size_t strideA, size_t strideB, size_t strideC)
{
    __shared__ __align__(16) float As[BK][BM + PAD];
    __shared__ __align__(16) float Bs[BK][BN + PAD];

    const int bx = blockIdx.x;           // N tile
    const int by = blockIdx.y;           // M tile
    const float* Abase = A + blockIdx.z * strideA + (size_t)by * BM * K;
    const float* Bbase;
    if (TRANSB) Bbase = Bp + blockIdx.z * strideB + (size_t)bx * BN * K;
    else        Bbase = Bp + blockIdx.z * strideB + (size_t)bx * BN;
    float* Cbase = C + blockIdx.z * strideC + (size_t)by * BM * N + (size_t)bx * BN;

    const int tid = threadIdx.x;
    const int tx = tid & 15;             // 0..15  -> N direction
    const int ty = tid >> 4;             // 0..15  -> M direction

    float acc[TM][TN] = {};

    for (int k0 = 0; k0 < K; k0 += BK) {
        // ---- load A tile (128 rows x 16 k), transpose into As[k][m] ----
        #pragma unroll
        for (int i = 0; i < 2; i++) {
            int f   = tid + i * 256;     // 0..511 float4 index
            int row = f >> 2;            // 0..127
            int cv  = f & 3;             // float4 within the 16-wide k slice
            float4 v = *reinterpret_cast<const float4*>(
                Abase + (size_t)row * K + k0 + cv * 4);
            As[cv * 4 + 0][row] = v.x;
            As[cv * 4 + 1][row] = v.y;
            As[cv * 4 + 2][row] = v.z;
            As[cv * 4 + 3][row] = v.w;
        }
        // ---- load B tile ----
        if (TRANSB) {
            #pragma unroll
            for (int i = 0; i < 2; i++) {
                int f   = tid + i * 256;
                int row = f >> 2;        // n within tile
                int cv  = f & 3;
                float4 v = *reinterpret_cast<const float4*>(
                    Bbase + (size_t)row * K + k0 + cv * 4);
                Bs[cv * 4 + 0][row] = v.x;
                Bs[cv * 4 + 1][row] = v.y;
                Bs[cv * 4 + 2][row] = v.z;
                Bs[cv * 4 + 3][row] = v.w;
            }
        } else {
            #pragma unroll
            for (int i = 0; i < 2; i++) {
                int f   = tid + i * 256;
                int row = f >> 5;        // k within tile (BN/4 = 32 float4/row)
                int cv  = f & 31;
                float4 v = *reinterpret_cast<const float4*>(
                    Bbase + (size_t)(k0 + row) * N + cv * 4);
                *reinterpret_cast<float4*>(&Bs[row][cv * 4]) = v;
            }
        }
        __syncthreads();

        // ---- compute ----
        #pragma unroll
        for (int kk = 0; kk < BK; kk++) {
            float a[TM], b[TN];
            *reinterpret_cast<float4*>(&a[0]) =
                *reinterpret_cast<const float4*>(&As[kk][ty * TM]);
            *reinterpret_cast<float4*>(&a[4]) =
                *reinterpret_cast<const float4*>(&As[kk][ty * TM + 4]);
            *reinterpret_cast<float4*>(&b[0]) =
                *reinterpret_cast<const float4*>(&Bs[kk][tx * TN]);
            *reinterpret_cast<float4*>(&b[4]) =
                *reinterpret_cast<const float4*>(&Bs[kk][tx * TN + 4]);
            #pragma unroll
            for (int i = 0; i < TM; i++)
                #pragma unroll
                for (int j = 0; j < TN; j++)
                    acc[i][j] += a[i] * b[j];
        }
        __syncthreads();
    }

    // ---- epilogue: scale, bias, store ----
    #pragma unroll
    for (int i = 0; i < TM; i++) {
        int m = ty * TM + i;
        #pragma unroll
        for (int j = 0; j < TN; j += 4) {
            int n = tx * TN + j;
            float4 v;
            v.x = acc[i][j + 0] * scale;
            v.y = acc[i][j + 1] * scale;
            v.z = acc[i][j + 2] * scale;
            v.w = acc[i][j + 3] * scale;
            if (bias) {
                int gn = bx * BN + n;
                v.x += bias[gn + 0];
                v.y += bias[gn + 1];
                v.z += bias[gn + 2];
                v.w += bias[gn + 3];
            }
            *reinterpret_cast<float4*>(Cbase + (size_t)m * N + n) = v;
        }
    }
}

// ---------------------------------------------------------------------------
// Row softmax over SEQ=2048 elements: one block (256 threads) per row.
// ---------------------------------------------------------------------------
__global__ void __launch_bounds__(256) softmax_kernel(float* __restrict__ alpha)
{
    __shared__ float redmax[8];
    __shared__ float redsum[8];

    float* row = alpha + (size_t)blockIdx.x * SEQ;
    const int tid = threadIdx.x;

    float4 v0 = reinterpret_cast<float4*>(row)[tid];
    float4 v1 = reinterpret_cast<float4*>(row)[tid + 256];

    // ---- max ----
    float m = fmaxf(fmaxf(fmaxf(v0.x, v0.y), fmaxf(v0.z, v0.w)),
                    fmaxf(fmaxf(v1.x, v1.y), fmaxf(v1.z, v1.w)));
    #pragma unroll
    for (int o = 16; o > 0; o >>= 1) m = fmaxf(m, __shfl_xor_sync(0xffffffffu, m, o));
    if ((tid & 31) == 0) redmax[tid >> 5] = m;
    __syncthreads();
    if (tid < 32) {
        float t = (tid < 8) ? redmax[tid] : -INFINITY;
        #pragma unroll
        for (int o = 4; o > 0; o >>= 1) t = fmaxf(t, __shfl_xor_sync(0xffffffffu, t, o));
        if (tid == 0) redmax[0] = t;
    }
    __syncthreads();
    m = redmax[0];

    // ---- exp + sum ----
    v0.x = expf(v0.x - m); v0.y = expf(v0.y - m);
    v0.z = expf(v0.z - m); v0.w = expf(v0.w - m);
    v1.x = expf(v1.x - m); v1.y = expf(v1.y - m);
    v1.z = expf(v1.z - m); v1.w = expf(v1.w - m);
    float s = v0.x + v0.y + v0.z + v0.w + v1.x + v1.y + v1.z + v1.w;
    #pragma unroll
    for (int o = 16; o > 0; o >>= 1) s += __shfl_xor_sync(0xffffffffu, s, o);
    if ((tid & 31) == 0) redsum[tid >> 5] = s;
    __syncthreads();
    if (tid < 32) {
        float t = (tid < 8) ? redsum[tid] : 0.0f;
        #pragma unroll
        for (int o = 4; o > 0; o >>= 1) t += __shfl_xor_sync(0xffffffffu, t, o);
        if (tid == 0) redsum[0] = t;
    }
    __syncthreads();
    float inv = 1.0f / redsum[0];

    v0.x *= inv; v0.y *= inv; v0.z *= inv; v0.w *= inv;
    v1.x *= inv; v1.y *= inv; v1.z *= inv; v1.w *= inv;
    reinterpret_cast<float4*>(row)[tid]       = v0;
    reinterpret_cast<float4*>(row)[tid + 256] = v1;
}

// ---------------------------------------------------------------------------
// kernel_launch
// ---------------------------------------------------------------------------
extern "C" void kernel_launch(void* const* d_in, const int* in_sizes, int n_in,
                              void* d_out, int out_size)
{
    (void)in_sizes; (void)n_in; (void)out_size;

    const float* x  = (const float*)d_in[0];
    const float* Wq = (const float*)d_in[1];
    const float* bq = (const float*)d_in[2];
    const float* Wk = (const float*)d_in[3];
    const float* bk = (const float*)d_in[4];
    const float* Wv = (const float*)d_in[5];
    const float* bv = (const float*)d_in[6];
    const float* Wp = (const float*)d_in[7];
    const float* bp = (const float*)d_in[8];
    float* out = (float*)d_out;

    float *Q, *K, *V, *O, *alpha;
    cudaGetSymbolAddress((void**)&Q,     g_Q);
    cudaGetSymbolAddress((void**)&K,     g_K);
    cudaGetSymbolAddress((void**)&V,     g_V);
    cudaGetSymbolAddress((void**)&O,     g_O);
    cudaGetSymbolAddress((void**)&alpha, g_alpha);

    const float inv_scale = (float)(1.0 / sqrt((double)DIM));

    // 1) Q/K/V projections: [16384,768] = x @ W^T + b
    {
        dim3 grid(DIM / BN, MROWS / BM, 1);
        sgemm_kernel<true><<<grid, 256>>>(x, Wq, bq, Q, MROWS, DIM, DIM, 1.0f, 0, 0, 0);
        sgemm_kernel<true><<<grid, 256>>>(x, Wk, bk, K, MROWS, DIM, DIM, 1.0f, 0, 0, 0);
        sgemm_kernel<true><<<grid, 256>>>(x, Wv, bv, V, MROWS, DIM, DIM, 1.0f, 0, 0, 0);
    }

    // 2) scores: alpha[b,q,k] = (Q Kt) / sqrt(D)   (batched, TRANSB)
    {
        dim3 grid(SEQ / BN, SEQ / BM, BATCH);
        sgemm_kernel<true><<<grid, 256>>>(Q, K, nullptr, alpha,
                                          SEQ, SEQ, DIM, inv_scale,
                                          (size_t)SEQ * DIM, (size_t)SEQ * DIM,
                                          (size_t)SEQ * SEQ);
    }

    // 3) row softmax
    softmax_kernel<<<BATCH * SEQ, 256>>>(alpha);

    // 4) O = alpha @ V   (batched, non-transposed B)
    {
        dim3 grid(DIM / BN, SEQ / BM, BATCH);
        sgemm_kernel<false><<<grid, 256>>>(alpha, V, nullptr, O,
                                           SEQ, DIM, SEQ, 1.0f,
                                           (size_t)SEQ * SEQ, (size_t)SEQ * DIM,
                                           (size_t)SEQ * DIM);
    }

    // 5) out = O @ Wp^T + bp
    {
        dim3 grid(DIM / BN, MROWS / BM, 1);
        sgemm_kernel<true><<<grid, 256>>>(O, Wp, bp, out, MROWS, DIM, DIM, 1.0f, 0, 0, 0);
    }
}

// round 2
// speedup vs baseline: 2.3686x; 2.3686x over previous
#include <cuda_runtime.h>
#include <cuda_bf16.h>
#include <math.h>
#include <stdint.h>

// Problem constants
#define BATCH 8
#define SEQ   2048
#define DIM   768
#define MROWS (BATCH * SEQ)   // 16384

// GEMM tiling
#define BM 128
#define BN 128
#define BK 16
#define SPAD 8                 // smem row stride = BM + 8 = 136 -> conflict-free frag loads

// ---------------------------------------------------------------------------
// Scratch (allocation-free contract: __device__ globals)
// ---------------------------------------------------------------------------
__device__ float g_Q[(size_t)MROWS * DIM];
__device__ float g_K[(size_t)MROWS * DIM];
__device__ float g_V[(size_t)MROWS * DIM];
__device__ float g_O[(size_t)MROWS * DIM];
__device__ float g_alpha[(size_t)BATCH * SEQ * SEQ];

// ---------------------------------------------------------------------------
// Helpers
// ---------------------------------------------------------------------------
__device__ __forceinline__ uint32_t f2tf32(float f) {
    uint32_t u;
    asm("cvt.rna.tf32.f32 %0, %1;" : "=r"(u) : "f"(f));
    return u;
}

__device__ __forceinline__ void mma_tf32(float* d, const uint32_t* a, const uint32_t* b) {
    asm volatile(
        "mma.sync.aligned.m16n8k8.row.col.f32.tf32.tf32.f32 "
        "{%0,%1,%2,%3}, {%4,%5,%6,%7}, {%8,%9}, {%0,%1,%2,%3};"
        : "+f"(d[0]), "+f"(d[1]), "+f"(d[2]), "+f"(d[3])
        : "r"(a[0]), "r"(a[1]), "r"(a[2]), "r"(a[3]),
          "r"(b[0]), "r"(b[1]));
}

// ---------------------------------------------------------------------------
// TF32 tensor-core GEMM:
//   C[m,n] = scale * sum_k A[m,k] * B'[k,n]  (+ bias[n])
//   TRANSB=true : B is [N,K] row-major (B'[k,n] = B[n,k])  -- x @ W^T, Q @ K^T
//   TRANSB=false: B is [K,N] row-major                     -- alpha @ V
// 256 threads = 8 warps; warp tile 64x32 (warps 2 in M x 4 in N);
// per warp 4x4 grid of m16n8k8 fragments.
// ---------------------------------------------------------------------------
template<bool TRANSB>
__global__ void __launch_bounds__(256) tf32_gemm_kernel(
    const float* __restrict__ A, const float* __restrict__ Bp,
    const float* __restrict__ bias, float* __restrict__ C,
    int M, int N, int K, float scale,
    size_t strideA, size_t strideB, size_t strideC)
{
    __shared__ uint32_t As[BK][BM + SPAD];
    __shared__ uint32_t Bs[BK][BN + SPAD];

    const int bx = blockIdx.x;           // N tile
    const int by = blockIdx.y;           // M tile
    const float* Abase = A + blockIdx.z * strideA + (size_t)by * BM * K;
    const float* Bbase;
    if (TRANSB) Bbase = Bp + blockIdx.z * strideB + (size_t)bx * BN * K;
    else        Bbase = Bp + blockIdx.z * strideB + (size_t)bx * BN;
    float* Cbase = C + blockIdx.z * strideC + (size_t)by * BM * N + (size_t)bx * BN;

    const int tid  = threadIdx.x;
    const int lane = tid & 31;
    const int wid  = tid >> 5;           // 0..7
    const int warpM = wid & 1;           // 2 warp rows (64 each)
    const int warpN = wid >> 1;          // 4 warp cols (32 each)

    float acc[4][4][4] = {};             // [mt][nt][frag]

    // ---- gmem tile fetch (into registers) ----
    float4 pa[2], pb[2];
    auto fetch = [&](int k0) {
        #pragma unroll
        for (int i = 0; i < 2; i++) {
            int f   = tid + i * 256;
            int row = f >> 2;
            int cv  = f & 3;
            pa[i] = *reinterpret_cast<const float4*>(
                Abase + (size_t)row * K + k0 + cv * 4);
        }
        if (TRANSB) {
            #pragma unroll
            for (int i = 0; i < 2; i++) {
                int f   = tid + i * 256;
                int row = f >> 2;
                int cv  = f & 3;
                pb[i] = *reinterpret_cast<const float4*>(
                    Bbase + (size_t)row * K + k0 + cv * 4);
            }
        } else {
            #pragma unroll
            for (int i = 0; i < 2; i++) {
                int f   = tid + i * 256;
                int row = f >> 5;        // k (0..15)
                int cv  = f & 31;        // n float4 (0..31)
                pb[i] = *reinterpret_cast<const float4*>(
                    Bbase + (size_t)(k0 + row) * N + cv * 4);
            }
        }
    };

    // ---- smem tile commit (tf32 conversion happens here, once per element) ----
    auto commit = [&]() {
        #pragma unroll
        for (int i = 0; i < 2; i++) {
            int f   = tid + i * 256;
            int row = f >> 2;
            int cv  = f & 3;
            As[cv * 4 + 0][row] = f2tf32(pa[i].x);
            As[cv * 4 + 1][row] = f2tf32(pa[i].y);
            As[cv * 4 + 2][row] = f2tf32(pa[i].z);
            As[cv * 4 + 3][row] = f2tf32(pa[i].w);
        }
        if (TRANSB) {
            #pragma unroll
            for (int i = 0; i < 2; i++) {
                int f   = tid + i * 256;
                int row = f >> 2;
                int cv  = f & 3;
                Bs[cv * 4 + 0][row] = f2tf32(pb[i].x);
                Bs[cv * 4 + 1][row] = f2tf32(pb[i].y);
                Bs[cv * 4 + 2][row] = f2tf32(pb[i].z);
                Bs[cv * 4 + 3][row] = f2tf32(pb[i].w);
            }
        } else {
            #pragma unroll
            for (int i = 0; i < 2; i++) {
                int f   = tid + i * 256;
                int row = f >> 5;
                int cv  = f & 31;
                Bs[row][cv * 4 + 0] = f2tf32(pb[i].x);
                Bs[row][cv * 4 + 1] = f2tf32(pb[i].y);
                Bs[row][cv * 4 + 2] = f2tf32(pb[i].z);
                Bs[row][cv * 4 + 3] = f2tf32(pb[i].w);
            }
        }
    };

    fetch(0);
    commit();
    __syncthreads();

    for (int k0 = 0; k0 < K; k0 += BK) {
        const bool more = (k0 + BK) < K;
        if (more) fetch(k0 + BK);

        // ---- compute on the resident tile ----
        #pragma unroll
        for (int kk = 0; kk < BK; kk += 8) {
            uint32_t afrag[4][4];
            uint32_t bfrag[4][2];
            const int kA = kk + (lane & 3);
            const int rA = (lane >> 2);
            #pragma unroll
            for (int mt = 0; mt < 4; mt++) {
                int m = warpM * 64 + mt * 16 + rA;
                afrag[mt][0] = As[kA][m];
                afrag[mt][1] = As[kA][m + 8];
                afrag[mt][2] = As[kA + 4][m];
                afrag[mt][3] = As[kA + 4][m + 8];
            }
            #pragma unroll
            for (int nt = 0; nt < 4; nt++) {
                int n = warpN * 32 + nt * 8 + rA;
                bfrag[nt][0] = Bs[kA][n];
                bfrag[nt][1] = Bs[kA + 4][n];
            }
            #pragma unroll
            for (int mt = 0; mt < 4; mt++)
                #pragma unroll
                for (int nt = 0; nt < 4; nt++)
                    mma_tf32(acc[mt][nt], afrag[mt], bfrag[nt]);
        }

        __syncthreads();
        if (more) {
            commit();
            __syncthreads();
        }
    }

    // ---- epilogue: scale, bias, store (float2 per fragment row) ----
    const int r0 = (lane >> 2);
    const int c0 = 2 * (lane & 3);
    #pragma unroll
    for (int mt = 0; mt < 4; mt++) {
        #pragma unroll
        for (int nt = 0; nt < 4; nt++) {
            int m = warpM * 64 + mt * 16 + r0;
            int n = warpN * 32 + nt * 8 + c0;
            float b0 = 0.f, b1 = 0.f;
            if (bias) {
                b0 = bias[bx * BN + n];
                b1 = bias[bx * BN + n + 1];
            }
            float2 v0, v1;
            v0.x = acc[mt][nt][0] * scale + b0;
            v0.y = acc[mt][nt][1] * scale + b1;
            v1.x = acc[mt][nt][2] * scale + b0;
            v1.y = acc[mt][nt][3] * scale + b1;
            *reinterpret_cast<float2*>(Cbase + (size_t)m * N + n)       = v0;
            *reinterpret_cast<float2*>(Cbase + (size_t)(m + 8) * N + n) = v1;
        }
    }
}

// ---------------------------------------------------------------------------
// Row softmax over SEQ=2048 elements: one block (256 threads) per row.
// ---------------------------------------------------------------------------
__global__ void __launch_bounds__(256) softmax_kernel(float* __restrict__ alpha)
{
    __shared__ float redmax[8];
    __shared__ float redsum[8];

    float* row = alpha + (size_t)blockIdx.x * SEQ;
    const int tid = threadIdx.x;

    float4 v0 = reinterpret_cast<float4*>(row)[tid];
    float4 v1 = reinterpret_cast<float4*>(row)[tid + 256];

    float m = fmaxf(fmaxf(fmaxf(v0.x, v0.y), fmaxf(v0.z, v0.w)),
                    fmaxf(fmaxf(v1.x, v1.y), fmaxf(v1.z, v1.w)));
    #pragma unroll
    for (int o = 16; o > 0; o >>= 1) m = fmaxf(m, __shfl_xor_sync(0xffffffffu, m, o));
    if ((tid & 31) == 0) redmax[tid >> 5] = m;
    __syncthreads();
    if (tid < 32) {
        float t = (tid < 8) ? redmax[tid] : -INFINITY;
        #pragma unroll
        for (int o = 4; o > 0; o >>= 1) t = fmaxf(t, __shfl_xor_sync(0xffffffffu, t, o));
        if (tid == 0) redmax[0] = t;
    }
    __syncthreads();
    m = redmax[0];

    v0.x = expf(v0.x - m); v0.y = expf(v0.y - m);
    v0.z = expf(v0.z - m); v0.w = expf(v0.w - m);
    v1.x = expf(v1.x - m); v1.y = expf(v1.y - m);
    v1.z = expf(v1.z - m); v1.w = expf(v1.w - m);
    float s = v0.x + v0.y + v0.z + v0.w + v1.x + v1.y + v1.z + v1.w;
    #pragma unroll
    for (int o = 16; o > 0; o >>= 1) s += __shfl_xor_sync(0xffffffffu, s, o);
    if ((tid & 31) == 0) redsum[tid >> 5] = s;
    __syncthreads();
    if (tid < 32) {
        float t = (tid < 8) ? redsum[tid] : 0.0f;
        #pragma unroll
        for (int o = 4; o > 0; o >>= 1) t += __shfl_xor_sync(0xffffffffu, t, o);
        if (tid == 0) redsum[0] = t;
    }
    __syncthreads();
    float inv = 1.0f / redsum[0];

    v0.x *= inv; v0.y *= inv; v0.z *= inv; v0.w *= inv;
    v1.x *= inv; v1.y *= inv; v1.z *= inv; v1.w *= inv;
    reinterpret_cast<float4*>(row)[tid]       = v0;
    reinterpret_cast<float4*>(row)[tid + 256] = v1;
}

// ---------------------------------------------------------------------------
// kernel_launch
// ---------------------------------------------------------------------------
extern "C" void kernel_launch(void* const* d_in, const int* in_sizes, int n_in,
                              void* d_out, int out_size)
{
    (void)in_sizes; (void)n_in; (void)out_size;

    const float* x  = (const float*)d_in[0];
    const float* Wq = (const float*)d_in[1];
    const float* bq = (const float*)d_in[2];
    const float* Wk = (const float*)d_in[3];
    const float* bk = (const float*)d_in[4];
    const float* Wv = (const float*)d_in[5];
    const float* bv = (const float*)d_in[6];
    const float* Wp = (const float*)d_in[7];
    const float* bp = (const float*)d_in[8];
    float* out = (float*)d_out;

    float *Q, *K, *V, *O, *alpha;
    cudaGetSymbolAddress((void**)&Q,     g_Q);
    cudaGetSymbolAddress((void**)&K,     g_K);
    cudaGetSymbolAddress((void**)&V,     g_V);
    cudaGetSymbolAddress((void**)&O,     g_O);
    cudaGetSymbolAddress((void**)&alpha, g_alpha);

    const float inv_scale = (float)(1.0 / sqrt((double)DIM));

    // 1) Q/K/V projections: [16384,768] = x @ W^T + b
    {
        dim3 grid(DIM / BN, MROWS / BM, 1);
        tf32_gemm_kernel<true><<<grid, 256>>>(x, Wq, bq, Q, MROWS, DIM, DIM, 1.0f, 0, 0, 0);
        tf32_gemm_kernel<true><<<grid, 256>>>(x, Wk, bk, K, MROWS, DIM, DIM, 1.0f, 0, 0, 0);
        tf32_gemm_kernel<true><<<grid, 256>>>(x, Wv, bv, V, MROWS, DIM, DIM, 1.0f, 0, 0, 0);
    }

    // 2) scores: alpha[b,q,k] = (Q K^T) / sqrt(D)
    {
        dim3 grid(SEQ / BN, SEQ / BM, BATCH);
        tf32_gemm_kernel<true><<<grid, 256>>>(Q, K, nullptr, alpha,
                                              SEQ, SEQ, DIM, inv_scale,
                                              (size_t)SEQ * DIM, (size_t)SEQ * DIM,
                                              (size_t)SEQ * SEQ);
    }

    // 3) row softmax
    softmax_kernel<<<BATCH * SEQ, 256>>>(alpha);

    // 4) O = alpha @ V
    {
        dim3 grid(DIM / BN, SEQ / BM, BATCH);
        tf32_gemm_kernel<false><<<grid, 256>>>(alpha, V, nullptr, O,
                                               SEQ, DIM, SEQ, 1.0f,
                                               (size_t)SEQ * SEQ, (size_t)SEQ * DIM,
                                               (size_t)SEQ * DIM);
    }

    // 5) out = O @ Wp^T + bp
    {
        dim3 grid(DIM / BN, MROWS / BM, 1);
        tf32_gemm_kernel<true><<<grid, 256>>>(O, Wp, bp, out, MROWS, DIM, DIM, 1.0f, 0, 0, 0);
    }
}

// round 3
// speedup vs baseline: 2.4837x; 1.0486x over previous
#include <cuda_runtime.h>
#include <cuda_bf16.h>
#include <math.h>
#include <stdint.h>

// Problem constants
#define BATCH 8
#define SEQ   2048
#define DIM   768
#define MROWS (BATCH * SEQ)   // 16384

// GEMM tiling
#define BM 128
#define BN 128
#define BK 16
#define SPAD 8                 // smem row stride = BM + 8 = 136 -> conflict-free frag loads

// ---------------------------------------------------------------------------
// Scratch (allocation-free contract: __device__ globals)
// ---------------------------------------------------------------------------
__device__ float g_Q[(size_t)MROWS * DIM];
__device__ float g_K[(size_t)MROWS * DIM];
__device__ float g_V[(size_t)MROWS * DIM];
__device__ float g_O[(size_t)MROWS * DIM];
__device__ float g_alpha[(size_t)BATCH * SEQ * SEQ];

// ---------------------------------------------------------------------------
// Helpers
// ---------------------------------------------------------------------------
__device__ __forceinline__ uint32_t f2tf32(float f) {
    uint32_t u;
    asm("cvt.rna.tf32.f32 %0, %1;" : "=r"(u) : "f"(f));
    return u;
}

__device__ __forceinline__ void mma_tf32(float* d, const uint32_t* a, const uint32_t* b) {
    asm volatile(
        "mma.sync.aligned.m16n8k8.row.col.f32.tf32.tf32.f32 "
        "{%0,%1,%2,%3}, {%4,%5,%6,%7}, {%8,%9}, {%0,%1,%2,%3};"
        : "+f"(d[0]), "+f"(d[1]), "+f"(d[2]), "+f"(d[3])
        : "r"(a[0]), "r"(a[1]), "r"(a[2]), "r"(a[3]),
          "r"(b[0]), "r"(b[1]));
}

// ---------------------------------------------------------------------------
// TF32 tensor-core GEMM, double-buffered smem pipeline.
//   C[m,n] = scale * sum_k A[m,k] * B'[k,n]  (+ bias[n])
//   TRANSB=true : B is [N,K] row-major  -- x @ W^T, Q @ K^T
//   TRANSB=false: B is [K,N] row-major  -- alpha @ V
// 256 threads = 8 warps; warp tile 64x32; per warp 4x4 m16n8k8 fragments.
// ---------------------------------------------------------------------------
template<bool TRANSB>
__global__ void __launch_bounds__(256) tf32_gemm_kernel(
    const float* __restrict__ A, const float* __restrict__ Bp,
    const float* __restrict__ bias, float* __restrict__ C,
    int M, int N, int K, float scale,
    size_t strideA, size_t strideB, size_t strideC)
{
    __shared__ uint32_t As[2][BK][BM + SPAD];
    __shared__ uint32_t Bs[2][BK][BN + SPAD];

    const int bx = blockIdx.x;           // N tile
    const int by = blockIdx.y;           // M tile
    const float* Abase = A + blockIdx.z * strideA + (size_t)by * BM * K;
    const float* Bbase;
    if (TRANSB) Bbase = Bp + blockIdx.z * strideB + (size_t)bx * BN * K;
    else        Bbase = Bp + blockIdx.z * strideB + (size_t)bx * BN;
    float* Cbase = C + blockIdx.z * strideC + (size_t)by * BM * N + (size_t)bx * BN;

    const int tid  = threadIdx.x;
    const int lane = tid & 31;
    const int wid  = tid >> 5;           // 0..7
    const int warpM = wid & 1;           // 2 warp rows (64 each)
    const int warpN = wid >> 1;          // 4 warp cols (32 each)

    float acc[4][4][4] = {};             // [mt][nt][frag]

    // ---- gmem tile fetch (into registers) ----
    float4 pa[2], pb[2];
    auto fetch = [&](int k0) {
        #pragma unroll
        for (int i = 0; i < 2; i++) {
            int f   = tid + i * 256;
            int row = f >> 2;
            int cv  = f & 3;
            pa[i] = *reinterpret_cast<const float4*>(
                Abase + (size_t)row * K + k0 + cv * 4);
        }
        if (TRANSB) {
            #pragma unroll
            for (int i = 0; i < 2; i++) {
                int f   = tid + i * 256;
                int row = f >> 2;
                int cv  = f & 3;
                pb[i] = *reinterpret_cast<const float4*>(
                    Bbase + (size_t)row * K + k0 + cv * 4);
            }
        } else {
            #pragma unroll
            for (int i = 0; i < 2; i++) {
                int f   = tid + i * 256;
                int row = f >> 5;        // k (0..15)
                int cv  = f & 31;        // n float4 (0..31)
                pb[i] = *reinterpret_cast<const float4*>(
                    Bbase + (size_t)(k0 + row) * N + cv * 4);
            }
        }
    };

    // ---- smem tile commit (tf32 conversion happens here, once per element) ----
    auto commit = [&](int buf) {
        #pragma unroll
        for (int i = 0; i < 2; i++) {
            int f   = tid + i * 256;
            int row = f >> 2;
            int cv  = f & 3;
            As[buf][cv * 4 + 0][row] = f2tf32(pa[i].x);
            As[buf][cv * 4 + 1][row] = f2tf32(pa[i].y);
            As[buf][cv * 4 + 2][row] = f2tf32(pa[i].z);
            As[buf][cv * 4 + 3][row] = f2tf32(pa[i].w);
        }
        if (TRANSB) {
            #pragma unroll
            for (int i = 0; i < 2; i++) {
                int f   = tid + i * 256;
                int row = f >> 2;
                int cv  = f & 3;
                Bs[buf][cv * 4 + 0][row] = f2tf32(pb[i].x);
                Bs[buf][cv * 4 + 1][row] = f2tf32(pb[i].y);
                Bs[buf][cv * 4 + 2][row] = f2tf32(pb[i].z);
                Bs[buf][cv * 4 + 3][row] = f2tf32(pb[i].w);
            }
        } else {
            #pragma unroll
            for (int i = 0; i < 2; i++) {
                int f   = tid + i * 256;
                int row = f >> 5;
                int cv  = f & 31;
                Bs[buf][row][cv * 4 + 0] = f2tf32(pb[i].x);
                Bs[buf][row][cv * 4 + 1] = f2tf32(pb[i].y);
                Bs[buf][row][cv * 4 + 2] = f2tf32(pb[i].z);
                Bs[buf][row][cv * 4 + 3] = f2tf32(pb[i].w);
            }
        }
    };

    // ---- compute one resident BK-tile ----
    auto compute = [&](int buf) {
        #pragma unroll
        for (int kk = 0; kk < BK; kk += 8) {
            uint32_t afrag[4][4];
            uint32_t bfrag[4][2];
            const int kA = kk + (lane & 3);
            const int rA = (lane >> 2);
            #pragma unroll
            for (int mt = 0; mt < 4; mt++) {
                int m = warpM * 64 + mt * 16 + rA;
                afrag[mt][0] = As[buf][kA][m];
                afrag[mt][1] = As[buf][kA][m + 8];
                afrag[mt][2] = As[buf][kA + 4][m];
                afrag[mt][3] = As[buf][kA + 4][m + 8];
            }
            #pragma unroll
            for (int nt = 0; nt < 4; nt++) {
                int n = warpN * 32 + nt * 8 + rA;
                bfrag[nt][0] = Bs[buf][kA][n];
                bfrag[nt][1] = Bs[buf][kA + 4][n];
            }
            #pragma unroll
            for (int mt = 0; mt < 4; mt++)
                #pragma unroll
                for (int nt = 0; nt < 4; nt++)
                    mma_tf32(acc[mt][nt], afrag[mt], bfrag[nt]);
        }
    };

    // ---- pipelined mainloop: one __syncthreads per BK step ----
    fetch(0);
    commit(0);
    __syncthreads();

    int buf = 0;
    for (int k0 = 0; k0 < K; k0 += BK) {
        const bool more = (k0 + BK) < K;
        if (more) fetch(k0 + BK);     // LDGs in flight...
        compute(buf);                 // ...hidden under tensor work
        if (more) commit(buf ^ 1);    // writes other buffer: no WAR with compute(buf)
        __syncthreads();
        buf ^= 1;
    }

    // ---- epilogue: scale, bias, store (float2 per fragment row) ----
    const int r0 = (lane >> 2);
    const int c0 = 2 * (lane & 3);
    #pragma unroll
    for (int mt = 0; mt < 4; mt++) {
        #pragma unroll
        for (int nt = 0; nt < 4; nt++) {
            int m = warpM * 64 + mt * 16 + r0;
            int n = warpN * 32 + nt * 8 + c0;
            float b0 = 0.f, b1 = 0.f;
            if (bias) {
                b0 = bias[bx * BN + n];
                b1 = bias[bx * BN + n + 1];
            }
            float2 v0, v1;
            v0.x = acc[mt][nt][0] * scale + b0;
            v0.y = acc[mt][nt][1] * scale + b1;
            v1.x = acc[mt][nt][2] * scale + b0;
            v1.y = acc[mt][nt][3] * scale + b1;
            *reinterpret_cast<float2*>(Cbase + (size_t)m * N + n)       = v0;
            *reinterpret_cast<float2*>(Cbase + (size_t)(m + 8) * N + n) = v1;
        }
    }
}

// ---------------------------------------------------------------------------
// Row softmax over SEQ=2048 elements: one block (256 threads) per row.
// ---------------------------------------------------------------------------
__global__ void __launch_bounds__(256) softmax_kernel(float* __restrict__ alpha)
{
    __shared__ float redmax[8];
    __shared__ float redsum[8];

    float* row = alpha + (size_t)blockIdx.x * SEQ;
    const int tid = threadIdx.x;

    float4 v0 = reinterpret_cast<float4*>(row)[tid];
    float4 v1 = reinterpret_cast<float4*>(row)[tid + 256];

    float m = fmaxf(fmaxf(fmaxf(v0.x, v0.y), fmaxf(v0.z, v0.w)),
                    fmaxf(fmaxf(v1.x, v1.y), fmaxf(v1.z, v1.w)));
    #pragma unroll
    for (int o = 16; o > 0; o >>= 1) m = fmaxf(m, __shfl_xor_sync(0xffffffffu, m, o));
    if ((tid & 31) == 0) redmax[tid >> 5] = m;
    __syncthreads();
    if (tid < 32) {
        float t = (tid < 8) ? redmax[tid] : -INFINITY;
        #pragma unroll
        for (int o = 4; o > 0; o >>= 1) t = fmaxf(t, __shfl_xor_sync(0xffffffffu, t, o));
        if (tid == 0) redmax[0] = t;
    }
    __syncthreads();
    m = redmax[0];

    v0.x = __expf(v0.x - m); v0.y = __expf(v0.y - m);
    v0.z = __expf(v0.z - m); v0.w = __expf(v0.w - m);
    v1.x = __expf(v1.x - m); v1.y = __expf(v1.y - m);
    v1.z = __expf(v1.z - m); v1.w = __expf(v1.w - m);
    float s = v0.x + v0.y + v0.z + v0.w + v1.x + v1.y + v1.z + v1.w;
    #pragma unroll
    for (int o = 16; o > 0; o >>= 1) s += __shfl_xor_sync(0xffffffffu, s, o);
    if ((tid & 31) == 0) redsum[tid >> 5] = s;
    __syncthreads();
    if (tid < 32) {
        float t = (tid < 8) ? redsum[tid] : 0.0f;
        #pragma unroll
        for (int o = 4; o > 0; o >>= 1) t += __shfl_xor_sync(0xffffffffu, t, o);
        if (tid == 0) redsum[0] = t;
    }
    __syncthreads();
    float inv = 1.0f / redsum[0];

    v0.x *= inv; v0.y *= inv; v0.z *= inv; v0.w *= inv;
    v1.x *= inv; v1.y *= inv; v1.z *= inv; v1.w *= inv;
    reinterpret_cast<float4*>(row)[tid]       = v0;
    reinterpret_cast<float4*>(row)[tid + 256] = v1;
}

// ---------------------------------------------------------------------------
// kernel_launch
// ---------------------------------------------------------------------------
extern "C" void kernel_launch(void* const* d_in, const int* in_sizes, int n_in,
                              void* d_out, int out_size)
{
    (void)in_sizes; (void)n_in; (void)out_size;

    const float* x  = (const float*)d_in[0];
    const float* Wq = (const float*)d_in[1];
    const float* bq = (const float*)d_in[2];
    const float* Wk = (const float*)d_in[3];
    const float* bk = (const float*)d_in[4];
    const float* Wv = (const float*)d_in[5];
    const float* bv = (const float*)d_in[6];
    const float* Wp = (const float*)d_in[7];
    const float* bp = (const float*)d_in[8];
    float* out = (float*)d_out;

    float *Q, *K, *V, *O, *alpha;
    cudaGetSymbolAddress((void**)&Q,     g_Q);
    cudaGetSymbolAddress((void**)&K,     g_K);
    cudaGetSymbolAddress((void**)&V,     g_V);
    cudaGetSymbolAddress((void**)&O,     g_O);
    cudaGetSymbolAddress((void**)&alpha, g_alpha);

    const float inv_scale = (float)(1.0 / sqrt((double)DIM));

    // 1) Q/K/V projections: [16384,768] = x @ W^T + b
    {
        dim3 grid(DIM / BN, MROWS / BM, 1);
        tf32_gemm_kernel<true><<<grid, 256>>>(x, Wq, bq, Q, MROWS, DIM, DIM, 1.0f, 0, 0, 0);
        tf32_gemm_kernel<true><<<grid, 256>>>(x, Wk, bk, K, MROWS, DIM, DIM, 1.0f, 0, 0, 0);
        tf32_gemm_kernel<true><<<grid, 256>>>(x, Wv, bv, V, MROWS, DIM, DIM, 1.0f, 0, 0, 0);
    }

    // 2) scores: alpha[b,q,k] = (Q K^T) / sqrt(D)
    {
        dim3 grid(SEQ / BN, SEQ / BM, BATCH);
        tf32_gemm_kernel<true><<<grid, 256>>>(Q, K, nullptr, alpha,
                                              SEQ, SEQ, DIM, inv_scale,
                                              (size_t)SEQ * DIM, (size_t)SEQ * DIM,
                                              (size_t)SEQ * SEQ);
    }

    // 3) row softmax
    softmax_kernel<<<BATCH * SEQ, 256>>>(alpha);

    // 4) O = alpha @ V
    {
        dim3 grid(DIM / BN, SEQ / BM, BATCH);
        tf32_gemm_kernel<false><<<grid, 256>>>(alpha, V, nullptr, O,
                                               SEQ, DIM, SEQ, 1.0f,
                                               (size_t)SEQ * SEQ, (size_t)SEQ * DIM,
                                               (size_t)SEQ * DIM);
    }

    // 5) out = O @ Wp^T + bp
    {
        dim3 grid(DIM / BN, MROWS / BM, 1);
        tf32_gemm_kernel<true><<<grid, 256>>>(O, Wp, bp, out, MROWS, DIM, DIM, 1.0f, 0, 0, 0);
    }
}

// round 6
// speedup vs baseline: 6.5146x; 2.6230x over previous
#include <cuda_runtime.h>
#include <cuda_fp16.h>
#include <math.h>
#include <stdint.h>

// Problem constants
#define BATCH 8
#define SEQ   2048
#define DIM   768
#define MROWS (BATCH * SEQ)   // 16384

// GEMM tiling
#define BM 128
#define BN 128
#define BKH 32                 // k-chunk in halves
#define STAGES 3
#define ROWB 80                // smem bytes per row: 64B data + 16B pad (bank-spread)
#define TILEB (128 * ROWB)     // 10240 B per operand tile
#define STAGEB (2 * TILEB)
#define SMEM_BYTES (STAGES * STAGEB)   // 61440

// ---------------------------------------------------------------------------
// Scratch (allocation-free contract: __device__ globals), all fp16
// ---------------------------------------------------------------------------
__device__ __half g_xh [(size_t)MROWS * DIM];
__device__ __half g_Wqh[DIM * DIM];
__device__ __half g_Wkh[DIM * DIM];
__device__ __half g_Wvh[DIM * DIM];
__device__ __half g_Wph[DIM * DIM];
__device__ __half g_Qh [(size_t)MROWS * DIM];
__device__ __half g_Kh [(size_t)MROWS * DIM];
__device__ __half g_Vth[(size_t)BATCH * DIM * SEQ];   // [b][d][s]
__device__ __half g_Oh [(size_t)MROWS * DIM];
__device__ __half g_Ah [(size_t)BATCH * SEQ * SEQ];   // attention matrix

// ---------------------------------------------------------------------------
// Helpers
// ---------------------------------------------------------------------------
__device__ __forceinline__ uint32_t smem_u32(const void* p) {
    uint32_t a;
    asm("{ .reg .u64 t; cvta.to.shared.u64 t, %1; cvt.u32.u64 %0, t; }" : "=r"(a) : "l"(p));
    return a;
}

__device__ __forceinline__ void cpasync16(uint32_t dst, const void* src) {
    asm volatile("cp.async.cg.shared.global [%0], [%1], 16;" :: "r"(dst), "l"(src) : "memory");
}

__device__ __forceinline__ void ldm_x4(uint32_t* r, uint32_t addr) {
    asm volatile("ldmatrix.sync.aligned.m8n8.x4.shared.b16 {%0,%1,%2,%3}, [%4];"
                 : "=r"(r[0]), "=r"(r[1]), "=r"(r[2]), "=r"(r[3]) : "r"(addr));
}

__device__ __forceinline__ void mma_f16(float* d, const uint32_t* a, const uint32_t* b) {
    asm volatile(
        "mma.sync.aligned.m16n8k16.row.col.f32.f16.f16.f32 "
        "{%0,%1,%2,%3}, {%4,%5,%6,%7}, {%8,%9}, {%0,%1,%2,%3};"
        : "+f"(d[0]), "+f"(d[1]), "+f"(d[2]), "+f"(d[3])
        : "r"(a[0]), "r"(a[1]), "r"(a[2]), "r"(a[3]), "r"(b[0]), "r"(b[1]));
}

// ---------------------------------------------------------------------------
// fp32 -> fp16 converter (grid-stride over float4 groups)
// ---------------------------------------------------------------------------
__global__ void __launch_bounds__(256) cvt_f2h(const float* __restrict__ in,
                                               __half* __restrict__ out, int n4)
{
    for (int i = blockIdx.x * blockDim.x + threadIdx.x; i < n4; i += gridDim.x * blockDim.x) {
        float4 v = reinterpret_cast<const float4*>(in)[i];
        __half2 h0 = __floats2half2_rn(v.x, v.y);
        __half2 h1 = __floats2half2_rn(v.z, v.w);
        reinterpret_cast<__half2*>(out)[2 * i]     = h0;
        reinterpret_cast<__half2*>(out)[2 * i + 1] = h1;
    }
}

// ---------------------------------------------------------------------------
// FP16 tensor-core GEMM: C[m,n] = scale * sum_k A[m,k]*B[n,k] (+ bias[n])
//   A: [M,K] K-major fp16 (batched via strideA), B: [N,K] K-major fp16.
//   OUTMODE 0: fp16 output, row-major [*, ldC]
//   OUTMODE 1: fp16 output transposed into g_Vth layout [b][d][s]
//   OUTMODE 2: fp32 output, row-major [*, ldC]  (final projection)
// 256 threads = 8 warps (2 M x 4 N), warp tile 64x32, m16n8k16 fragments.
// cp.async 3-stage pipeline; ldmatrix.x4 fragment loads.
// ---------------------------------------------------------------------------
template<int OUTMODE>
__global__ void __launch_bounds__(256, 2) hgemm_kernel(
    const __half* __restrict__ A, const __half* __restrict__ B,
    const float* __restrict__ bias, void* __restrict__ Cv,
    int ldC, int K, float scale,
    size_t strideA, size_t strideB, size_t strideC)
{
    extern __shared__ __align__(16) char smem[];
    const uint32_t sbase = smem_u32(smem);
    const int tid  = threadIdx.x;
    const int lane = tid & 31;
    const int wid  = tid >> 5;
    const int warpM = wid & 1;     // 2 warp rows (64 m each)
    const int warpN = wid >> 1;    // 4 warp cols (32 n each)
    const int bx = blockIdx.x, by = blockIdx.y, bz = blockIdx.z;

    const __half* Ab = A + bz * strideA + (size_t)(by * BM) * K;
    const __half* Bb = B + bz * strideB + (size_t)(bx * BN) * K;

    // cp.async assignment: thread covers rows (tid>>2) and (tid>>2)+64, 16B col (tid&3)
    const int r0 = tid >> 2;       // 0..63
    const int kc = tid & 3;        // 0..3 (16B units within 64B row)

    const int nc = K / BKH;

    auto prefetch = [&](int c) {
        const int s = c % STAGES;
        if (c < nc) {
            const __half* ap = Ab + (size_t)r0 * K + c * BKH + kc * 8;
            const __half* bp = Bb + (size_t)r0 * K + c * BKH + kc * 8;
            const uint32_t da = sbase + s * STAGEB + r0 * ROWB + kc * 16;
            const uint32_t db = da + TILEB;
            cpasync16(da,             ap);
            cpasync16(da + 64 * ROWB, ap + (size_t)64 * K);
            cpasync16(db,             bp);
            cpasync16(db + 64 * ROWB, bp + (size_t)64 * K);
        }
        asm volatile("cp.async.commit_group;" ::: "memory");
    };

    float acc[4][4][4];
    #pragma unroll
    for (int i = 0; i < 4; i++)
        #pragma unroll
        for (int j = 0; j < 4; j++)
            #pragma unroll
            for (int q = 0; q < 4; q++) acc[i][j][q] = 0.0f;

    prefetch(0);
    prefetch(1);

    for (int c = 0; c < nc; c++) {
        asm volatile("cp.async.wait_group %0;" :: "n"(STAGES - 2) : "memory");
        __syncthreads();                       // stage c resident for all warps

        const int s = c % STAGES;
        const uint32_t sa = sbase + s * STAGEB;
        const uint32_t sb = sa + TILEB;

        #pragma unroll
        for (int kt = 0; kt < 2; kt++) {       // two k16 sub-steps per 32-k chunk
            uint32_t af[4][4], bf[4][2];
            // A fragments: ldmatrix.x4 per m16 block
            #pragma unroll
            for (int mt = 0; mt < 4; mt++) {
                const int m = warpM * 64 + mt * 16 + (lane & 15);
                const int k = kt * 16 + 8 * (lane >> 4);
                ldm_x4(af[mt], sa + m * ROWB + k * 2);
            }
            // B fragments: 2x ldmatrix.x4, each covers two n8 blocks
            #pragma unroll
            for (int nb = 0; nb < 2; nb++) {
                const int n = warpN * 32 + nb * 16 + (lane & 7) + 8 * (lane >> 4);
                const int k = kt * 16 + 8 * ((lane >> 3) & 1);
                uint32_t r[4];
                ldm_x4(r, sb + n * ROWB + k * 2);
                bf[nb * 2][0]     = r[0]; bf[nb * 2][1]     = r[1];
                bf[nb * 2 + 1][0] = r[2]; bf[nb * 2 + 1][1] = r[3];
            }
            #pragma unroll
            for (int mt = 0; mt < 4; mt++)
                #pragma unroll
                for (int nt = 0; nt < 4; nt++)
                    mma_f16(acc[mt][nt], af[mt], bf[nt]);
        }
        // prefetch into stage (c+2)%3 == (c-1)%3: all warps finished reading it
        // (guaranteed by this iteration's __syncthreads above).
        prefetch(c + 2);
    }
    asm volatile("cp.async.wait_group 0;" ::: "memory");

    // ---- epilogue ----
    const int rbase = lane >> 2;          // 0..7
    const int cbase = 2 * (lane & 3);     // 0,2,4,6

    if (OUTMODE == 0 || OUTMODE == 2) {
        #pragma unroll
        for (int mt = 0; mt < 4; mt++) {
            #pragma unroll
            for (int nt = 0; nt < 4; nt++) {
                const int col = warpN * 32 + nt * 8 + cbase;
                const float b0 = bias ? bias[bx * BN + col]     : 0.0f;
                const float b1 = bias ? bias[bx * BN + col + 1] : 0.0f;
                #pragma unroll
                for (int h = 0; h < 2; h++) {
                    const int row = warpM * 64 + mt * 16 + rbase + 8 * h;
                    const float v0 = acc[mt][nt][2 * h + 0] * scale + b0;
                    const float v1 = acc[mt][nt][2 * h + 1] * scale + b1;
                    if (OUTMODE == 0) {
                        __half* Cb = (__half*)Cv + bz * strideC + (size_t)(by * BM) * ldC + bx * BN;
                        *reinterpret_cast<__half2*>(Cb + (size_t)row * ldC + col) =
                            __floats2half2_rn(v0, v1);
                    } else {
                        float* Cb = (float*)Cv + bz * strideC + (size_t)(by * BM) * ldC + bx * BN;
                        *reinterpret_cast<float2*>(Cb + (size_t)row * ldC + col) =
                            make_float2(v0, v1);
                    }
                }
            }
        }
    } else {
        // OUTMODE 1: transposed store into Vt[b][d][s] via smem staging
        __syncthreads();
        __half* Ts = reinterpret_cast<__half*>(smem);   // [128 d][136 m-halves]
        #pragma unroll
        for (int mt = 0; mt < 4; mt++) {
            #pragma unroll
            for (int nt = 0; nt < 4; nt++) {
                const int col = warpN * 32 + nt * 8 + cbase;
                const float b0 = bias ? bias[bx * BN + col]     : 0.0f;
                const float b1 = bias ? bias[bx * BN + col + 1] : 0.0f;
                #pragma unroll
                for (int h = 0; h < 2; h++) {
                    const int row = warpM * 64 + mt * 16 + rbase + 8 * h;
                    Ts[(col)     * 136 + row] = __float2half_rn(acc[mt][nt][2 * h + 0] * scale + b0);
                    Ts[(col + 1) * 136 + row] = __float2half_rn(acc[mt][nt][2 * h + 1] * scale + b1);
                }
            }
        }
        __syncthreads();
        const int mglob = by * BM;
        const int bb = mglob / SEQ;
        const int s0 = mglob % SEQ;
        __half* Ob = (__half*)Cv + ((size_t)bb * DIM + bx * BN) * SEQ + s0;
        const int d   = tid >> 1;
        const int seg = tid & 1;
        const uint4* src = reinterpret_cast<const uint4*>(Ts + d * 136 + seg * 64);
        uint4* dst = reinterpret_cast<uint4*>(Ob + (size_t)d * SEQ + seg * 64);
        #pragma unroll
        for (int i = 0; i < 8; i++) dst[i] = src[i];
    }
}

// ---------------------------------------------------------------------------
// Row softmax over SEQ=2048 fp16 elements: one block (256 threads) per row.
// ---------------------------------------------------------------------------
__global__ void __launch_bounds__(256) softmax_h(__half* __restrict__ alpha)
{
    __shared__ float redmax[8];
    __shared__ float redsum[8];

    __half* row = alpha + (size_t)blockIdx.x * SEQ;
    const int tid = threadIdx.x;

    uint4 u = reinterpret_cast<uint4*>(row)[tid];     // 8 halves
    __half2* hp = reinterpret_cast<__half2*>(&u);
    float v[8];
    #pragma unroll
    for (int i = 0; i < 4; i++) {
        float2 f = __half22float2(hp[i]);
        v[2 * i] = f.x; v[2 * i + 1] = f.y;
    }

    float m = v[0];
    #pragma unroll
    for (int i = 1; i < 8; i++) m = fmaxf(m, v[i]);
    #pragma unroll
    for (int o = 16; o > 0; o >>= 1) m = fmaxf(m, __shfl_xor_sync(0xffffffffu, m, o));
    if ((tid & 31) == 0) redmax[tid >> 5] = m;
    __syncthreads();
    if (tid < 32) {
        float t = (tid < 8) ? redmax[tid] : -INFINITY;
        #pragma unroll
        for (int o = 4; o > 0; o >>= 1) t = fmaxf(t, __shfl_xor_sync(0xffffffffu, t, o));
        if (tid == 0) redmax[0] = t;
    }
    __syncthreads();
    m = redmax[0];

    float s = 0.0f;
    #pragma unroll
    for (int i = 0; i < 8; i++) { v[i] = __expf(v[i] - m); s += v[i]; }
    #pragma unroll
    for (int o = 16; o > 0; o >>= 1) s += __shfl_xor_sync(0xffffffffu, s, o);
    if ((tid & 31) == 0) redsum[tid >> 5] = s;
    __syncthreads();
    if (tid < 32) {
        float t = (tid < 8) ? redsum[tid] : 0.0f;
        #pragma unroll
        for (int o = 4; o > 0; o >>= 1) t += __shfl_xor_sync(0xffffffffu, t, o);
        if (tid == 0) redsum[0] = t;
    }
    __syncthreads();
    const float inv = 1.0f / redsum[0];

    #pragma unroll
    for (int i = 0; i < 4; i++)
        hp[i] = __floats2half2_rn(v[2 * i] * inv, v[2 * i + 1] * inv);
    reinterpret_cast<uint4*>(row)[tid] = u;
}

// ---------------------------------------------------------------------------
// kernel_launch
// ---------------------------------------------------------------------------
extern "C" void kernel_launch(void* const* d_in, const int* in_sizes, int n_in,
                              void* d_out, int out_size)
{
    (void)in_sizes; (void)n_in; (void)out_size;

    const float* x  = (const float*)d_in[0];
    const float* Wq = (const float*)d_in[1];
    const float* bq = (const float*)d_in[2];
    const float* Wk = (const float*)d_in[3];
    const float* bk = (const float*)d_in[4];
    const float* Wv = (const float*)d_in[5];
    const float* bv = (const float*)d_in[6];
    const float* Wp = (const float*)d_in[7];
    const float* bp = (const float*)d_in[8];
    float* out = (float*)d_out;

    __half *xh, *Wqh, *Wkh, *Wvh, *Wph, *Qh, *Kh, *Vth, *Oh, *Ah;
    cudaGetSymbolAddress((void**)&xh,  g_xh);
    cudaGetSymbolAddress((void**)&Wqh, g_Wqh);
    cudaGetSymbolAddress((void**)&Wkh, g_Wkh);
    cudaGetSymbolAddress((void**)&Wvh, g_Wvh);
    cudaGetSymbolAddress((void**)&Wph, g_Wph);
    cudaGetSymbolAddress((void**)&Qh,  g_Qh);
    cudaGetSymbolAddress((void**)&Kh,  g_Kh);
    cudaGetSymbolAddress((void**)&Vth, g_Vth);
    cudaGetSymbolAddress((void**)&Oh,  g_Oh);
    cudaGetSymbolAddress((void**)&Ah,  g_Ah);

    static bool attr_set = false;
    if (!attr_set) {
        cudaFuncSetAttribute(hgemm_kernel<0>, cudaFuncAttributeMaxDynamicSharedMemorySize, SMEM_BYTES);
        cudaFuncSetAttribute(hgemm_kernel<1>, cudaFuncAttributeMaxDynamicSharedMemorySize, SMEM_BYTES);
        cudaFuncSetAttribute(hgemm_kernel<2>, cudaFuncAttributeMaxDynamicSharedMemorySize, SMEM_BYTES);
        attr_set = true;
    }

    const float inv_scale = (float)(1.0 / sqrt((double)DIM));

    // 0) fp32 -> fp16 conversions
    cvt_f2h<<<4096, 256>>>(x,  xh,  MROWS * DIM / 4);
    cvt_f2h<<<576,  256>>>(Wq, Wqh, DIM * DIM / 4);
    cvt_f2h<<<576,  256>>>(Wk, Wkh, DIM * DIM / 4);
    cvt_f2h<<<576,  256>>>(Wv, Wvh, DIM * DIM / 4);
    cvt_f2h<<<576,  256>>>(Wp, Wph, DIM * DIM / 4);

    // 1) Q/K projections -> fp16; V projection -> transposed fp16 Vt[b][d][s]
    {
        dim3 grid(DIM / BN, MROWS / BM, 1);
        hgemm_kernel<0><<<grid, 256, SMEM_BYTES>>>(xh, Wqh, bq, Qh, DIM, DIM, 1.0f, 0, 0, 0);
        hgemm_kernel<0><<<grid, 256, SMEM_BYTES>>>(xh, Wkh, bk, Kh, DIM, DIM, 1.0f, 0, 0, 0);
        hgemm_kernel<1><<<grid, 256, SMEM_BYTES>>>(xh, Wvh, bv, Vth, 0, DIM, 1.0f, 0, 0, 0);
    }

    // 2) scores: Ah[b,q,k] = (Q K^T) / sqrt(D)   (fp16 out)
    {
        dim3 grid(SEQ / BN, SEQ / BM, BATCH);
        hgemm_kernel<0><<<grid, 256, SMEM_BYTES>>>(Qh, Kh, nullptr, Ah,
                                                   SEQ, DIM, inv_scale,
                                                   (size_t)SEQ * DIM, (size_t)SEQ * DIM,
                                                   (size_t)SEQ * SEQ);
    }

    // 3) row softmax (fp16 in/out, fp32 math)
    softmax_h<<<BATCH * SEQ, 256>>>(Ah);

    // 4) O[b,q,d] = alpha[b,q,:] @ Vt[b,d,:]^T  (fp16 out)
    {
        dim3 grid(DIM / BN, SEQ / BM, BATCH);
        hgemm_kernel<0><<<grid, 256, SMEM_BYTES>>>(Ah, Vth, nullptr, Oh,
                                                   DIM, SEQ, 1.0f,
                                                   (size_t)SEQ * SEQ, (size_t)DIM * SEQ,
                                                   (size_t)SEQ * DIM);
    }

    // 5) out = O @ Wp^T + bp  (fp32 out, direct to d_out)
    {
        dim3 grid(DIM / BN, MROWS / BM, 1);
        hgemm_kernel<2><<<grid, 256, SMEM_BYTES>>>(Oh, Wph, bp, out, DIM, DIM, 1.0f, 0, 0, 0);
    }
}

// round 7
// speedup vs baseline: 7.9114x; 1.2144x over previous
#include <cuda_runtime.h>
#include <cuda_fp16.h>
#include <math.h>
#include <stdint.h>

// Problem constants
#define BATCH 8
#define SEQ   2048
#define DIM   768
#define MROWS (BATCH * SEQ)   // 16384

// GEMM tiling: CTA 128x128, 4 warps (2x2), warp tile 64x64
#define BM 128
#define BN 128
#define BKH 32                 // k-chunk in halves
#define STAGES 3
#define ROWB 80                // smem bytes per row: 64B data + 16B pad
#define TILEB (128 * ROWB)     // 10240 B per operand tile
#define STAGEB (2 * TILEB)
#define SMEM_BYTES (STAGES * STAGEB)   // 61440  (x2 CTAs = 120KB <= 227KB)

// ---------------------------------------------------------------------------
// Scratch (allocation-free contract: __device__ globals), all fp16
// ---------------------------------------------------------------------------
__device__ __half g_xh [(size_t)MROWS * DIM];
__device__ __half g_Wqh[DIM * DIM];
__device__ __half g_Wkh[DIM * DIM];
__device__ __half g_Wvh[DIM * DIM];
__device__ __half g_Wph[DIM * DIM];
__device__ __half g_Qh [(size_t)MROWS * DIM];
__device__ __half g_Kh [(size_t)MROWS * DIM];
__device__ __half g_Vth[(size_t)BATCH * DIM * SEQ];   // [b][d][s]
__device__ __half g_Oh [(size_t)MROWS * DIM];
__device__ __half g_Ah [(size_t)BATCH * SEQ * SEQ];   // attention matrix

// ---------------------------------------------------------------------------
// Helpers
// ---------------------------------------------------------------------------
__device__ __forceinline__ uint32_t smem_u32(const void* p) {
    uint32_t a;
    asm("{ .reg .u64 t; cvta.to.shared.u64 t, %1; cvt.u32.u64 %0, t; }" : "=r"(a) : "l"(p));
    return a;
}

__device__ __forceinline__ void cpasync16(uint32_t dst, const void* src) {
    asm volatile("cp.async.cg.shared.global [%0], [%1], 16;" :: "r"(dst), "l"(src) : "memory");
}

__device__ __forceinline__ void ldm_x4(uint32_t* r, uint32_t addr) {
    asm volatile("ldmatrix.sync.aligned.m8n8.x4.shared.b16 {%0,%1,%2,%3}, [%4];"
                 : "=r"(r[0]), "=r"(r[1]), "=r"(r[2]), "=r"(r[3]) : "r"(addr));
}

__device__ __forceinline__ void mma_f16(float* d, const uint32_t* a, const uint32_t* b) {
    asm volatile(
        "mma.sync.aligned.m16n8k16.row.col.f32.f16.f16.f32 "
        "{%0,%1,%2,%3}, {%4,%5,%6,%7}, {%8,%9}, {%0,%1,%2,%3};"
        : "+f"(d[0]), "+f"(d[1]), "+f"(d[2]), "+f"(d[3])
        : "r"(a[0]), "r"(a[1]), "r"(a[2]), "r"(a[3]), "r"(b[0]), "r"(b[1]));
}

// ---------------------------------------------------------------------------
// fp32 -> fp16 converters
// ---------------------------------------------------------------------------
__global__ void __launch_bounds__(256) cvt_f2h(const float* __restrict__ in,
                                               __half* __restrict__ out, int n4)
{
    for (int i = blockIdx.x * blockDim.x + threadIdx.x; i < n4; i += gridDim.x * blockDim.x) {
        float4 v = reinterpret_cast<const float4*>(in)[i];
        reinterpret_cast<__half2*>(out)[2 * i]     = __floats2half2_rn(v.x, v.y);
        reinterpret_cast<__half2*>(out)[2 * i + 1] = __floats2half2_rn(v.z, v.w);
    }
}

// All 4 weights in one launch: blockIdx.y selects the matrix.
__global__ void __launch_bounds__(256) cvt_weights(
    const float* __restrict__ w0, const float* __restrict__ w1,
    const float* __restrict__ w2, const float* __restrict__ w3,
    __half* __restrict__ o0, __half* __restrict__ o1,
    __half* __restrict__ o2, __half* __restrict__ o3, int n4)
{
    const float* in  = (blockIdx.y == 0) ? w0 : (blockIdx.y == 1) ? w1 : (blockIdx.y == 2) ? w2 : w3;
    __half*      out = (blockIdx.y == 0) ? o0 : (blockIdx.y == 1) ? o1 : (blockIdx.y == 2) ? o2 : o3;
    for (int i = blockIdx.x * blockDim.x + threadIdx.x; i < n4; i += gridDim.x * blockDim.x) {
        float4 v = reinterpret_cast<const float4*>(in)[i];
        reinterpret_cast<__half2*>(out)[2 * i]     = __floats2half2_rn(v.x, v.y);
        reinterpret_cast<__half2*>(out)[2 * i + 1] = __floats2half2_rn(v.z, v.w);
    }
}

// ---------------------------------------------------------------------------
// FP16 tensor-core GEMM: C[m,n] = scale * sum_k A[m,k]*B[n,k] (+ bias[n])
//   A: [M,K] K-major fp16 (batched via strideA), B: [N,K] K-major fp16.
//   OUTMODE 0: fp16 output, row-major [*, ldC]
//   OUTMODE 1: fp16 output transposed into g_Vth layout [b][d][s]
//   OUTMODE 2: fp32 output, row-major [*, ldC]  (final projection)
// 128 threads = 4 warps (2 M x 2 N), warp tile 64x64, m16n8k16 fragments.
// cp.async 3-stage pipeline; ldmatrix.x4 fragment loads. 2 CTAs/SM.
// ---------------------------------------------------------------------------
template<int OUTMODE>
__global__ void __launch_bounds__(128, 2) hgemm_kernel(
    const __half* __restrict__ A, const __half* __restrict__ B,
    const float* __restrict__ bias, void* __restrict__ Cv,
    int ldC, int K, float scale,
    size_t strideA, size_t strideB, size_t strideC)
{
    extern __shared__ __align__(16) char smem[];
    const uint32_t sbase = smem_u32(smem);
    const int tid  = threadIdx.x;
    const int lane = tid & 31;
    const int wid  = tid >> 5;
    const int warpM = wid & 1;     // 2 warp rows (64 m each)
    const int warpN = wid >> 1;    // 2 warp cols (64 n each)
    const int bx = blockIdx.x, by = blockIdx.y, bz = blockIdx.z;

    const __half* Ab = A + bz * strideA + (size_t)(by * BM) * K;
    const __half* Bb = B + bz * strideB + (size_t)(bx * BN) * K;

    // cp.async: thread covers rows r0+32*{0..3}, 16B col (tid&3), for A and B
    const int r0 = tid >> 2;       // 0..31
    const int kc = tid & 3;        // 0..3

    const int nc = K / BKH;

    auto prefetch = [&](int c) {
        const int s = c % STAGES;
        if (c < nc) {
            const __half* ap = Ab + (size_t)r0 * K + c * BKH + kc * 8;
            const __half* bp = Bb + (size_t)r0 * K + c * BKH + kc * 8;
            const uint32_t da = sbase + s * STAGEB + r0 * ROWB + kc * 16;
            const uint32_t db = da + TILEB;
            #pragma unroll
            for (int rr = 0; rr < 4; rr++) {
                cpasync16(da + rr * 32 * ROWB, ap + (size_t)(rr * 32) * K);
                cpasync16(db + rr * 32 * ROWB, bp + (size_t)(rr * 32) * K);
            }
        }
        asm volatile("cp.async.commit_group;" ::: "memory");
    };

    float acc[4][8][4];
    #pragma unroll
    for (int i = 0; i < 4; i++)
        #pragma unroll
        for (int j = 0; j < 8; j++)
            #pragma unroll
            for (int q = 0; q < 4; q++) acc[i][j][q] = 0.0f;

    prefetch(0);
    prefetch(1);

    for (int c = 0; c < nc; c++) {
        asm volatile("cp.async.wait_group %0;" :: "n"(STAGES - 2) : "memory");
        __syncthreads();                       // stage c resident for all warps

        const int s = c % STAGES;
        const uint32_t sa = sbase + s * STAGEB;
        const uint32_t sb = sa + TILEB;

        #pragma unroll
        for (int kt = 0; kt < 2; kt++) {       // two k16 sub-steps per 32-k chunk
            uint32_t af[4][4], bf[8][2];
            // A fragments: ldmatrix.x4 per m16 block (4 blocks of 64 rows)
            #pragma unroll
            for (int mt = 0; mt < 4; mt++) {
                const int m = warpM * 64 + mt * 16 + (lane & 15);
                const int k = kt * 16 + 8 * (lane >> 4);
                ldm_x4(af[mt], sa + m * ROWB + k * 2);
            }
            // B fragments: 4x ldmatrix.x4, each covers two n8 blocks (64 cols)
            #pragma unroll
            for (int nb = 0; nb < 4; nb++) {
                const int n = warpN * 64 + nb * 16 + (lane & 7) + 8 * (lane >> 4);
                const int k = kt * 16 + 8 * ((lane >> 3) & 1);
                uint32_t r[4];
                ldm_x4(r, sb + n * ROWB + k * 2);
                bf[nb * 2][0]     = r[0]; bf[nb * 2][1]     = r[1];
                bf[nb * 2 + 1][0] = r[2]; bf[nb * 2 + 1][1] = r[3];
            }
            #pragma unroll
            for (int mt = 0; mt < 4; mt++)
                #pragma unroll
                for (int nt = 0; nt < 8; nt++)
                    mma_f16(acc[mt][nt], af[mt], bf[nt]);
        }
        prefetch(c + 2);   // stage (c+2)%3 was finished being read before this iter's barrier
    }
    asm volatile("cp.async.wait_group 0;" ::: "memory");

    // ---- epilogue ----
    const int rbase = lane >> 2;          // 0..7
    const int cbase = 2 * (lane & 3);     // 0,2,4,6

    if (OUTMODE == 0 || OUTMODE == 2) {
        #pragma unroll
        for (int mt = 0; mt < 4; mt++) {
            #pragma unroll
            for (int nt = 0; nt < 8; nt++) {
                const int col = warpN * 64 + nt * 8 + cbase;
                const float b0 = bias ? bias[bx * BN + col]     : 0.0f;
                const float b1 = bias ? bias[bx * BN + col + 1] : 0.0f;
                #pragma unroll
                for (int h = 0; h < 2; h++) {
                    const int row = warpM * 64 + mt * 16 + rbase + 8 * h;
                    const float v0 = acc[mt][nt][2 * h + 0] * scale + b0;
                    const float v1 = acc[mt][nt][2 * h + 1] * scale + b1;
                    if (OUTMODE == 0) {
                        __half* Cb = (__half*)Cv + bz * strideC + (size_t)(by * BM) * ldC + bx * BN;
                        *reinterpret_cast<__half2*>(Cb + (size_t)row * ldC + col) =
                            __floats2half2_rn(v0, v1);
                    } else {
                        float* Cb = (float*)Cv + bz * strideC + (size_t)(by * BM) * ldC + bx * BN;
                        *reinterpret_cast<float2*>(Cb + (size_t)row * ldC + col) =
                            make_float2(v0, v1);
                    }
                }
            }
        }
    } else {
        // OUTMODE 1: transposed store into Vt[b][d][s] via smem staging
        __syncthreads();
        __half* Ts = reinterpret_cast<__half*>(smem);   // [128 d][136 m-halves]
        #pragma unroll
        for (int mt = 0; mt < 4; mt++) {
            #pragma unroll
            for (int nt = 0; nt < 8; nt++) {
                const int col = warpN * 64 + nt * 8 + cbase;
                const float b0 = bias ? bias[bx * BN + col]     : 0.0f;
                const float b1 = bias ? bias[bx * BN + col + 1] : 0.0f;
                #pragma unroll
                for (int h = 0; h < 2; h++) {
                    const int row = warpM * 64 + mt * 16 + rbase + 8 * h;
                    Ts[(col)     * 136 + row] = __float2half_rn(acc[mt][nt][2 * h + 0] * scale + b0);
                    Ts[(col + 1) * 136 + row] = __float2half_rn(acc[mt][nt][2 * h + 1] * scale + b1);
                }
            }
        }
        __syncthreads();
        const int mglob = by * BM;
        const int bb = mglob / SEQ;
        const int s0 = mglob % SEQ;
        __half* Ob = (__half*)Cv + ((size_t)bb * DIM + bx * BN) * SEQ + s0;
        const int d = tid;   // 0..127: one output d-column per thread
        const uint4* src = reinterpret_cast<const uint4*>(Ts + d * 136);
        uint4* dst = reinterpret_cast<uint4*>(Ob + (size_t)d * SEQ);
        #pragma unroll
        for (int i = 0; i < 16; i++) dst[i] = src[i];
    }
}

// ---------------------------------------------------------------------------
// Row softmax over SEQ=2048 fp16 elements: one block (256 threads) per row.
// ---------------------------------------------------------------------------
__global__ void __launch_bounds__(256) softmax_h(__half* __restrict__ alpha)
{
    __shared__ float redmax[8];
    __shared__ float redsum[8];

    __half* row = alpha + (size_t)blockIdx.x * SEQ;
    const int tid = threadIdx.x;

    uint4 u = reinterpret_cast<uint4*>(row)[tid];     // 8 halves
    __half2* hp = reinterpret_cast<__half2*>(&u);
    float v[8];
    #pragma unroll
    for (int i = 0; i < 4; i++) {
        float2 f = __half22float2(hp[i]);
        v[2 * i] = f.x; v[2 * i + 1] = f.y;
    }

    float m = v[0];
    #pragma unroll
    for (int i = 1; i < 8; i++) m = fmaxf(m, v[i]);
    #pragma unroll
    for (int o = 16; o > 0; o >>= 1) m = fmaxf(m, __shfl_xor_sync(0xffffffffu, m, o));
    if ((tid & 31) == 0) redmax[tid >> 5] = m;
    __syncthreads();
    if (tid < 32) {
        float t = (tid < 8) ? redmax[tid] : -INFINITY;
        #pragma unroll
        for (int o = 4; o > 0; o >>= 1) t = fmaxf(t, __shfl_xor_sync(0xffffffffu, t, o));
        if (tid == 0) redmax[0] = t;
    }
    __syncthreads();
    m = redmax[0];

    float s = 0.0f;
    #pragma unroll
    for (int i = 0; i < 8; i++) { v[i] = __expf(v[i] - m); s += v[i]; }
    #pragma unroll
    for (int o = 16; o > 0; o >>= 1) s += __shfl_xor_sync(0xffffffffu, s, o);
    if ((tid & 31) == 0) redsum[tid >> 5] = s;
    __syncthreads();
    if (tid < 32) {
        float t = (tid < 8) ? redsum[tid] : 0.0f;
        #pragma unroll
        for (int o = 4; o > 0; o >>= 1) t += __shfl_xor_sync(0xffffffffu, t, o);
        if (tid == 0) redsum[0] = t;
    }
    __syncthreads();
    const float inv = 1.0f / redsum[0];

    #pragma unroll
    for (int i = 0; i < 4; i++)
        hp[i] = __floats2half2_rn(v[2 * i] * inv, v[2 * i + 1] * inv);
    reinterpret_cast<uint4*>(row)[tid] = u;
}

// ---------------------------------------------------------------------------
// kernel_launch
// ---------------------------------------------------------------------------
extern "C" void kernel_launch(void* const* d_in, const int* in_sizes, int n_in,
                              void* d_out, int out_size)
{
    (void)in_sizes; (void)n_in; (void)out_size;

    const float* x  = (const float*)d_in[0];
    const float* Wq = (const float*)d_in[1];
    const float* bq = (const float*)d_in[2];
    const float* Wk = (const float*)d_in[3];
    const float* bk = (const float*)d_in[4];
    const float* Wv = (const float*)d_in[5];
    const float* bv = (const float*)d_in[6];
    const float* Wp = (const float*)d_in[7];
    const float* bp = (const float*)d_in[8];
    float* out = (float*)d_out;

    __half *xh, *Wqh, *Wkh, *Wvh, *Wph, *Qh, *Kh, *Vth, *Oh, *Ah;
    cudaGetSymbolAddress((void**)&xh,  g_xh);
    cudaGetSymbolAddress((void**)&Wqh, g_Wqh);
    cudaGetSymbolAddress((void**)&Wkh, g_Wkh);
    cudaGetSymbolAddress((void**)&Wvh, g_Wvh);
    cudaGetSymbolAddress((void**)&Wph, g_Wph);
    cudaGetSymbolAddress((void**)&Qh,  g_Qh);
    cudaGetSymbolAddress((void**)&Kh,  g_Kh);
    cudaGetSymbolAddress((void**)&Vth, g_Vth);
    cudaGetSymbolAddress((void**)&Oh,  g_Oh);
    cudaGetSymbolAddress((void**)&Ah,  g_Ah);

    static bool attr_set = false;
    if (!attr_set) {
        cudaFuncSetAttribute(hgemm_kernel<0>, cudaFuncAttributeMaxDynamicSharedMemorySize, SMEM_BYTES);
        cudaFuncSetAttribute(hgemm_kernel<1>, cudaFuncAttributeMaxDynamicSharedMemorySize, SMEM_BYTES);
        cudaFuncSetAttribute(hgemm_kernel<2>, cudaFuncAttributeMaxDynamicSharedMemorySize, SMEM_BYTES);
        attr_set = true;
    }

    const float inv_scale = (float)(1.0 / sqrt((double)DIM));

    // 0) fp32 -> fp16 conversions (x + all 4 weights in 2 launches)
    cvt_f2h<<<4096, 256>>>(x, xh, MROWS * DIM / 4);
    {
        dim3 grid(576, 4, 1);
        cvt_weights<<<grid, 256>>>(Wq, Wk, Wv, Wp, Wqh, Wkh, Wvh, Wph, DIM * DIM / 4);
    }

    // 1) Q/K projections -> fp16; V projection -> transposed fp16 Vt[b][d][s]
    {
        dim3 grid(DIM / BN, MROWS / BM, 1);
        hgemm_kernel<0><<<grid, 128, SMEM_BYTES>>>(xh, Wqh, bq, Qh, DIM, DIM, 1.0f, 0, 0, 0);
        hgemm_kernel<0><<<grid, 128, SMEM_BYTES>>>(xh, Wkh, bk, Kh, DIM, DIM, 1.0f, 0, 0, 0);
        hgemm_kernel<1><<<grid, 128, SMEM_BYTES>>>(xh, Wvh, bv, Vth, 0, DIM, 1.0f, 0, 0, 0);
    }

    // 2) scores: Ah[b,q,k] = (Q K^T) / sqrt(D)   (fp16 out)
    {
        dim3 grid(SEQ / BN, SEQ / BM, BATCH);
        hgemm_kernel<0><<<grid, 128, SMEM_BYTES>>>(Qh, Kh, nullptr, Ah,
                                                   SEQ, DIM, inv_scale,
                                                   (size_t)SEQ * DIM, (size_t)SEQ * DIM,
                                                   (size_t)SEQ * SEQ);
    }

    // 3) row softmax (fp16 in/out, fp32 math)
    softmax_h<<<BATCH * SEQ, 256>>>(Ah);

    // 4) O[b,q,d] = alpha[b,q,:] @ Vt[b,d,:]^T  (fp16 out)
    {
        dim3 grid(DIM / BN, SEQ / BM, BATCH);
        hgemm_kernel<0><<<grid, 128, SMEM_BYTES>>>(Ah, Vth, nullptr, Oh,
                                                   DIM, SEQ, 1.0f,
                                                   (size_t)SEQ * SEQ, (size_t)DIM * SEQ,
                                                   (size_t)SEQ * DIM);
    }

    // 5) out = O @ Wp^T + bp  (fp32 out, direct to d_out)
    {
        dim3 grid(DIM / BN, MROWS / BM, 1);
        hgemm_kernel<2><<<grid, 128, SMEM_BYTES>>>(Oh, Wph, bp, out, DIM, DIM, 1.0f, 0, 0, 0);
    }
}